// round 6
// baseline (speedup 1.0000x reference)
#include <cuda_runtime.h>
#include <cuda_bf16.h>
#include <cstdint>

#define N_ROWS 262144
#define DIM 64
#define KCODES 512
#define ROWS_PER_CTA 128
#define NCTA (N_ROWS / ROWS_PER_CTA)   /* 2048 */
#define THREADS 512
#define QCODES 128
#define NQ 4
#define EPS_CAND 1e-4f

#define XSTRIDE_B 144        /* bf16 tile row stride: 36 banks -> conflict-free */
#define DIST_STRIDE 136      /* floats; 136%32=8 -> conflict-free float2 stores */

#define OFF_XS   0                              /* [128][64] fp32   32768B */
#define OFF_XH   32768                          /* [128] rows bf16  18432B */
#define OFF_XL   (OFF_XH + 128*XSTRIDE_B)
#define OFF_WH   (OFF_XL + 128*XSTRIDE_B)       /* quarter codes hi */
#define OFF_WL   (OFF_WH + 128*XSTRIDE_B)
#define OFF_DIST (OFF_WL + 128*XSTRIDE_B)       /* [128][136] fp32  69632B */
#define OFF_W2   (OFF_DIST + 128*DIST_STRIDE*4)
#define OFF_SS   (OFF_W2 + 2048)
#define OFF_BIDX (OFF_SS + 512)
#define OFF_REDF (OFF_BIDX + 512)
#define SMEM_BYTES (OFF_REDF + 2048)            /* 181248B */

__device__ int   g_counts[KCODES];
__device__ float g_partials[NCTA];

// m16n8k16 row.col bf16 HMMA, fp32 accumulate (sm_80+ PTX, no 'a' features)
static __device__ __forceinline__ void mma_bf16(
    float& c0, float& c1, float& c2, float& c3,
    uint32_t a0, uint32_t a1, uint32_t a2, uint32_t a3,
    uint32_t b0, uint32_t b1)
{
    asm volatile(
        "mma.sync.aligned.m16n8k16.row.col.f32.bf16.bf16.f32 "
        "{%0,%1,%2,%3}, {%4,%5,%6,%7}, {%8,%9}, {%0,%1,%2,%3};"
        : "+f"(c0), "+f"(c1), "+f"(c2), "+f"(c3)
        : "r"(a0), "r"(a1), "r"(a2), "r"(a3), "r"(b0), "r"(b1));
}

// split x into bf16 hi + lo (x-hi exact in fp32); pack k-pairs (low16 = even k)
static __device__ __forceinline__ void split2pack(float x0, float x1,
                                                  uint32_t& hi, uint32_t& lo) {
    __nv_bfloat16 h0 = __float2bfloat16(x0);
    __nv_bfloat16 h1 = __float2bfloat16(x1);
    __nv_bfloat16 l0 = __float2bfloat16(x0 - __bfloat162float(h0));
    __nv_bfloat16 l1 = __float2bfloat16(x1 - __bfloat162float(h1));
    hi = (uint32_t)__bfloat16_as_ushort(h0) | ((uint32_t)__bfloat16_as_ushort(h1) << 16);
    lo = (uint32_t)__bfloat16_as_ushort(l0) | ((uint32_t)__bfloat16_as_ushort(l1) << 16);
}

__global__ void vq_prep() { g_counts[threadIdx.x] = 0; }

__global__ __launch_bounds__(THREADS, 1)
void vq_main(const float* __restrict__ X, const float* __restrict__ W,
             float* __restrict__ out)
{
    extern __shared__ char sm[];
    float* Xs    = (float*)(sm + OFF_XS);
    float* distq = (float*)(sm + OFF_DIST);
    float* w2s   = (float*)(sm + OFF_W2);
    float* Ss    = (float*)(sm + OFF_SS);
    int*   bidxs = (int*)  (sm + OFF_BIDX);
    float* redf  = (float*)(sm + OFF_REDF);

    const int tid = threadIdx.x;
    const int lane = tid & 31, wid = tid >> 5;
    const int g = lane >> 2, tig = lane & 3;     // fragment coords
    const int rt = wid & 7, ch = wid >> 3;       // row-tile, col-half
    const int bid = blockIdx.x;
    const size_t row0 = (size_t)bid * ROWS_PER_CTA;
    const float4* Wg4 = (const float4*)W;

    // --- stage X fp32 ---
    const float4* Xg4 = (const float4*)(X + row0 * DIM);
    float4* Xs4 = (float4*)Xs;
    for (int i = tid; i < ROWS_PER_CTA * 16; i += THREADS) Xs4[i] = Xg4[i];

    // --- w2: sequential-d fmaf chain (same as passing R4/R5 order) ---
    {
        float s = 0.f;
        #pragma unroll
        for (int qq = 0; qq < 16; ++qq) {
            float4 v = Wg4[tid * 16 + qq];
            s = fmaf(v.x, v.x, s); s = fmaf(v.y, v.y, s);
            s = fmaf(v.z, v.z, s); s = fmaf(v.w, v.w, s);
        }
        w2s[tid] = s;
    }
    __syncthreads();

    // --- X bf16 hi/lo splits ---
    for (int i = tid; i < ROWS_PER_CTA * 32; i += THREADS) {
        int r = i >> 5, k2 = i & 31;
        uint32_t hi, lo;
        split2pack(Xs[r * 64 + 2 * k2], Xs[r * 64 + 2 * k2 + 1], hi, lo);
        *(uint32_t*)(sm + OFF_XH + r * XSTRIDE_B + k2 * 4) = hi;
        *(uint32_t*)(sm + OFF_XL + r * XSTRIDE_B + k2 * 4) = lo;
    }
    // --- S: sequential-d fmaf chain ---
    if (tid < ROWS_PER_CTA) {
        float s = 0.f;
        const float4* xr = (const float4*)(Xs + tid * 64);
        #pragma unroll
        for (int qq = 0; qq < 16; ++qq) {
            float4 v = xr[qq];
            s = fmaf(v.x, v.x, s); s = fmaf(v.y, v.y, s);
            s = fmaf(v.z, v.z, s); s = fmaf(v.w, v.w, s);
        }
        Ss[tid] = s;
    }
    __syncthreads();

    const int mrow = tid >> 2, seg = tid & 3;    // min/rescue assignment
    float bestE = 3.4e38f; int bestI = 0x7fffffff;

    #pragma unroll 1
    for (int q = 0; q < NQ; ++q) {
        // --- stage W quarter hi/lo splits ---
        const float2* Wq2 = (const float2*)(W + (size_t)q * QCODES * DIM);
        for (int i = tid; i < QCODES * 32; i += THREADS) {
            int r = i >> 5, k2 = i & 31;
            float2 v = Wq2[r * 32 + k2];
            uint32_t hi, lo;
            split2pack(v.x, v.y, hi, lo);
            *(uint32_t*)(sm + OFF_WH + r * XSTRIDE_B + k2 * 4) = hi;
            *(uint32_t*)(sm + OFF_WL + r * XSTRIDE_B + k2 * 4) = lo;
        }
        __syncthreads();

        // --- 3-pass bf16 MMA mainloop: acc = Ah*Bh + Ah*Bl + Al*Bh ---
        float acc[8][4];
        #pragma unroll
        for (int t = 0; t < 8; ++t)
            acc[t][0] = acc[t][1] = acc[t][2] = acc[t][3] = 0.f;

        const uint32_t a_row = (uint32_t)(rt * 16 + g) * XSTRIDE_B;
        const uint32_t b_col = (uint32_t)(ch * 64 + g) * XSTRIDE_B;
        #pragma unroll
        for (int ks = 0; ks < 4; ++ks) {
            const uint32_t koff = (uint32_t)(ks * 16 + tig * 2) * 2;
            const uint32_t ao = a_row + koff;
            uint32_t ah0 = *(const uint32_t*)(sm + OFF_XH + ao);
            uint32_t ah1 = *(const uint32_t*)(sm + OFF_XH + ao + 8 * XSTRIDE_B);
            uint32_t ah2 = *(const uint32_t*)(sm + OFF_XH + ao + 16);
            uint32_t ah3 = *(const uint32_t*)(sm + OFF_XH + ao + 8 * XSTRIDE_B + 16);
            uint32_t al0 = *(const uint32_t*)(sm + OFF_XL + ao);
            uint32_t al1 = *(const uint32_t*)(sm + OFF_XL + ao + 8 * XSTRIDE_B);
            uint32_t al2 = *(const uint32_t*)(sm + OFF_XL + ao + 16);
            uint32_t al3 = *(const uint32_t*)(sm + OFF_XL + ao + 8 * XSTRIDE_B + 16);
            #pragma unroll
            for (int t = 0; t < 8; ++t) {
                const uint32_t bo = b_col + (uint32_t)(t * 8) * XSTRIDE_B + koff;
                uint32_t bh0 = *(const uint32_t*)(sm + OFF_WH + bo);
                uint32_t bh1 = *(const uint32_t*)(sm + OFF_WH + bo + 16);
                uint32_t bl0 = *(const uint32_t*)(sm + OFF_WL + bo);
                uint32_t bl1 = *(const uint32_t*)(sm + OFF_WL + bo + 16);
                mma_bf16(acc[t][0], acc[t][1], acc[t][2], acc[t][3],
                         ah0, ah1, ah2, ah3, bh0, bh1);
                mma_bf16(acc[t][0], acc[t][1], acc[t][2], acc[t][3],
                         ah0, ah1, ah2, ah3, bl0, bl1);
                mma_bf16(acc[t][0], acc[t][1], acc[t][2], acc[t][3],
                         al0, al1, al2, al3, bh0, bh1);
            }
        }

        // --- distances -> smem ---
        const int r_lo = rt * 16 + g, r_hi = r_lo + 8;
        const float S_lo = Ss[r_lo], S_hi = Ss[r_hi];
        #pragma unroll
        for (int t = 0; t < 8; ++t) {
            int c0 = ch * 64 + t * 8 + tig * 2;
            int code = q * QCODES + c0;
            float w20 = w2s[code], w21 = w2s[code + 1];
            float d00 = (S_lo + w20) - 2.0f * acc[t][0];
            float d01 = (S_lo + w21) - 2.0f * acc[t][1];
            float d10 = (S_hi + w20) - 2.0f * acc[t][2];
            float d11 = (S_hi + w21) - 2.0f * acc[t][3];
            *(float2*)(distq + r_lo * DIST_STRIDE + c0) = make_float2(d00, d01);
            *(float2*)(distq + r_hi * DIST_STRIDE + c0) = make_float2(d10, d11);
        }
        __syncthreads();

        // --- per-row approx min + exact rescue of candidates ---
        const float* dr = distq + mrow * DIST_STRIDE + seg * 32;
        float mn = 3.4e38f;
        #pragma unroll
        for (int i4 = 0; i4 < 8; ++i4) {
            float4 v = *(const float4*)(dr + i4 * 4);
            mn = fminf(mn, fminf(fminf(v.x, v.y), fminf(v.z, v.w)));
        }
        mn = fminf(mn, __shfl_xor_sync(0xffffffffu, mn, 1));
        mn = fminf(mn, __shfl_xor_sync(0xffffffffu, mn, 2));
        float thr = fminf(mn, bestE) + EPS_CAND;

        for (int j = 0; j < 32; ++j) {
            if (dr[j] <= thr) {
                int code = q * QCODES + seg * 32 + j;
                float dot = 0.f;
                const float4* xr = (const float4*)(Xs + mrow * 64);
                #pragma unroll
                for (int qq = 0; qq < 16; ++qq) {
                    float4 wv = Wg4[code * 16 + qq], xv = xr[qq];
                    dot = fmaf(xv.x, wv.x, dot); dot = fmaf(xv.y, wv.y, dot);
                    dot = fmaf(xv.z, wv.z, dot); dot = fmaf(xv.w, wv.w, dot);
                }
                float de = (Ss[mrow] + w2s[code]) - 2.0f * dot;  // exact chain
                if (de < bestE || (de == bestE && code < bestI)) {
                    bestE = de; bestI = code;
                }
            }
        }
        __syncthreads();   // before overwriting WH/WL/dist next quarter
    }

    // --- reduce exact (bestE, bestI) across the 4 seg-threads per row ---
    #pragma unroll
    for (int off = 1; off <= 2; off <<= 1) {
        float ov = __shfl_xor_sync(0xffffffffu, bestE, off);
        int   oi = __shfl_xor_sync(0xffffffffu, bestI, off);
        if (ov < bestE || (ov == bestE && oi < bestI)) { bestE = ov; bestI = oi; }
    }
    if (seg == 0) bidxs[mrow] = bestI;
    __syncthreads();

    // --- outputs: [loss | quantized N*64 | perplexity | indices N] ---
    // out_q = out + 1 is only 4B-aligned -> scalar STG.32 (R1 trap lesson).
    float* out_q = out + 1;
    float* out_i = out + 2 + (size_t)N_ROWS * DIM;

    if (tid < ROWS_PER_CTA) {
        int k = bidxs[tid];
        out_i[row0 + tid] = (float)k;
        atomicAdd(&g_counts[k], 1);
    }

    float sq = 0.f;
    for (int i = tid; i < ROWS_PER_CTA * 16; i += THREADS) {
        int rr = i >> 4, qq = i & 15;
        int k = bidxs[rr];
        float4 wv = Wg4[k * 16 + qq];
        float4 xv = ((const float4*)(Xs + rr * 64))[qq];
        float* dst = out_q + (row0 + rr) * DIM + qq * 4;
        dst[0] = wv.x; dst[1] = wv.y; dst[2] = wv.z; dst[3] = wv.w;
        float dx = wv.x - xv.x, dy = wv.y - xv.y;
        float dz = wv.z - xv.z, dw = wv.w - xv.w;
        sq += dx * dx + dy * dy + dz * dz + dw * dw;
    }
    redf[tid] = sq;
    __syncthreads();
    #pragma unroll
    for (int s = THREADS / 2; s > 0; s >>= 1) {
        if (tid < s) redf[tid] += redf[tid + s];
        __syncthreads();
    }
    if (tid == 0) g_partials[bid] = redf[0];
}

__global__ void vq_final(float* __restrict__ out) {
    __shared__ float sh[KCODES];
    int t = threadIdx.x;

    float p = (float)g_counts[t] * (1.0f / (float)N_ROWS);
    sh[t] = -p * logf(p + 1e-10f);
    __syncthreads();
    for (int s = KCODES / 2; s > 0; s >>= 1) {
        if (t < s) sh[t] += sh[t + s];
        __syncthreads();
    }
    float ent = sh[0];
    __syncthreads();

    float ps = 0.f;
    for (int i = t; i < NCTA; i += KCODES) ps += g_partials[i];
    sh[t] = ps;
    __syncthreads();
    for (int s = KCODES / 2; s > 0; s >>= 1) {
        if (t < s) sh[t] += sh[t + s];
        __syncthreads();
    }
    if (t == 0) {
        float mse = sh[0] / (float)((size_t)N_ROWS * DIM);
        out[0] = 1.25f * mse;
        out[1 + (size_t)N_ROWS * DIM] = expf(ent) / (float)KCODES;
    }
}

extern "C" void kernel_launch(void* const* d_in, const int* in_sizes, int n_in,
                              void* d_out, int out_size)
{
    const float* X = (const float*)d_in[0];
    const float* W = (const float*)d_in[1];
    if (n_in >= 2 && in_sizes[0] == KCODES * DIM) {
        X = (const float*)d_in[1];
        W = (const float*)d_in[0];
    }
    float* out = (float*)d_out;
    (void)out_size;

    cudaFuncSetAttribute(vq_main, cudaFuncAttributeMaxDynamicSharedMemorySize,
                         SMEM_BYTES);

    vq_prep<<<1, KCODES>>>();
    vq_main<<<NCTA, THREADS, SMEM_BYTES>>>(X, W, out);
    vq_final<<<1, KCODES>>>(out);
}

// round 9
// speedup vs baseline: 1.0051x; 1.0051x over previous
#include <cuda_runtime.h>
#include <cuda_bf16.h>
#include <cstdint>

#define N_ROWS 262144
#define DIM 64
#define KCODES 512
#define ROWS_PER_CTA 128
#define NCTA (N_ROWS / ROWS_PER_CTA)   /* 2048 */
#define THREADS 512
#define QCODES 128
#define NQ 4
#define EPS_CAND 1e-4f

#define XSTRIDE_B 144        /* bf16 tile row stride: 36 words -> LDSM conflict-free */

#define OFF_XS   0                              /* [128][64] fp32, 32768B */
#define OFF_XH   32768                          /* X hi bf16, 18432B */
#define OFF_XL   (OFF_XH + 128*XSTRIDE_B)       /* X lo */
#define OFF_WH   (OFF_XL + 128*XSTRIDE_B)       /* W quarter hi */
#define OFF_WL   (OFF_WH + 128*XSTRIDE_B)       /* W quarter lo */
#define OFF_RMIN (OFF_WL + 128*XSTRIDE_B)       /* [2][128] fp32 */
#define OFF_CV   (OFF_RMIN + 1024)              /* [2][128] fp32 */
#define OFF_CI   (OFF_CV + 1024)                /* [2][128] int  */
#define OFF_BIDX (OFF_CI + 1024)                /* [128] int */
#define OFF_REDF (OFF_BIDX + 512)               /* [512] fp32 */
#define OFF_W2   (OFF_REDF + 2048)              /* [512] fp32 */
#define OFF_SS   (OFF_W2 + 2048)                /* [128] fp32 */
#define SMEM_BYTES (OFF_SS + 512)               /* 115200B -> 2 CTA/SM (230400 <= 233472) */

__device__ int   g_counts[KCODES];
__device__ float g_partials[NCTA];

static __device__ __forceinline__ void mma_bf16(
    float& c0, float& c1, float& c2, float& c3,
    uint32_t a0, uint32_t a1, uint32_t a2, uint32_t a3,
    uint32_t b0, uint32_t b1)
{
    asm volatile(
        "mma.sync.aligned.m16n8k16.row.col.f32.bf16.bf16.f32 "
        "{%0,%1,%2,%3}, {%4,%5,%6,%7}, {%8,%9}, {%0,%1,%2,%3};"
        : "+f"(c0), "+f"(c1), "+f"(c2), "+f"(c3)
        : "r"(a0), "r"(a1), "r"(a2), "r"(a3), "r"(b0), "r"(b1));
}
#define LDSM_X4(r0, r1, r2, r3, addr) \
    asm volatile("ldmatrix.sync.aligned.m8n8.x4.shared.b16 {%0,%1,%2,%3}, [%4];" \
                 : "=r"(r0), "=r"(r1), "=r"(r2), "=r"(r3) : "r"(addr))

static __device__ __forceinline__ void split2pack(float x0, float x1,
                                                  uint32_t& hi, uint32_t& lo) {
    __nv_bfloat16 h0 = __float2bfloat16(x0);
    __nv_bfloat16 h1 = __float2bfloat16(x1);
    __nv_bfloat16 l0 = __float2bfloat16(x0 - __bfloat162float(h0));
    __nv_bfloat16 l1 = __float2bfloat16(x1 - __bfloat162float(h1));
    hi = (uint32_t)__bfloat16_as_ushort(h0) | ((uint32_t)__bfloat16_as_ushort(h1) << 16);
    lo = (uint32_t)__bfloat16_as_ushort(l0) | ((uint32_t)__bfloat16_as_ushort(l1) << 16);
}

__global__ void vq_prep() { g_counts[threadIdx.x] = 0; }

__global__ __launch_bounds__(THREADS, 2)
void vq_main(const float* __restrict__ X, const float* __restrict__ W,
             float* __restrict__ out)
{
    extern __shared__ char sm[];
    float* Xs    = (float*)(sm + OFF_XS);
    float* rmin  = (float*)(sm + OFF_RMIN);
    float* cV    = (float*)(sm + OFF_CV);
    int*   cI    = (int*)  (sm + OFF_CI);
    float* w2s   = (float*)(sm + OFF_W2);
    float* Ss    = (float*)(sm + OFF_SS);
    int*   bidxs = (int*)  (sm + OFF_BIDX);
    float* redf  = (float*)(sm + OFF_REDF);

    const int tid = threadIdx.x;
    const int lane = tid & 31, wid = tid >> 5;
    const int g = lane >> 2, tig = lane & 3;     // fragment coords
    const int rt = wid & 7, ch = wid >> 3;       // row-tile, col-half
    const int bid = blockIdx.x;
    const size_t row0 = (size_t)bid * ROWS_PER_CTA;
    const float4* Wg4 = (const float4*)W;

    const uint32_t smb = (uint32_t)__cvta_generic_to_shared(sm);
    // ldmatrix lane-address constants: A covers 16x16 (4 mats: r0-7/r8-15 x k0-7/k8-15),
    // B x4 covers two 8-col n-tiles (matching R6's verified fragment mapping).
    const uint32_t aconst = smb + (uint32_t)((rt * 16 + (lane & 15)) * XSTRIDE_B
                                             + (lane >> 4) * 16);
    const int bgrp = lane >> 3, bwin = lane & 7;
    const uint32_t bconst = smb + (uint32_t)((ch * 64 + (bgrp >> 1) * 8 + bwin) * XSTRIDE_B
                                             + (bgrp & 1) * 16);

    // --- stage X fp32 ---
    const float4* Xg4 = (const float4*)(X + row0 * DIM);
    float4* Xs4 = (float4*)Xs;
    for (int i = tid; i < ROWS_PER_CTA * 16; i += THREADS) Xs4[i] = Xg4[i];

    // --- w2: sequential-d fmaf chain (identical to passing R4/R6) ---
    {
        float s = 0.f;
        #pragma unroll
        for (int qq = 0; qq < 16; ++qq) {
            float4 v = Wg4[tid * 16 + qq];
            s = fmaf(v.x, v.x, s); s = fmaf(v.y, v.y, s);
            s = fmaf(v.z, v.z, s); s = fmaf(v.w, v.w, s);
        }
        w2s[tid] = s;
    }
    __syncthreads();

    // --- X bf16 hi/lo splits ---
    for (int i = tid; i < ROWS_PER_CTA * 32; i += THREADS) {
        int r = i >> 5, k2 = i & 31;
        uint32_t hi, lo;
        split2pack(Xs[r * 64 + 2 * k2], Xs[r * 64 + 2 * k2 + 1], hi, lo);
        *(uint32_t*)(sm + OFF_XH + r * XSTRIDE_B + k2 * 4) = hi;
        *(uint32_t*)(sm + OFF_XL + r * XSTRIDE_B + k2 * 4) = lo;
    }
    // --- S: sequential-d fmaf chain ---
    if (tid < ROWS_PER_CTA) {
        float s = 0.f;
        const float4* xr = (const float4*)(Xs + tid * 64);
        #pragma unroll
        for (int qq = 0; qq < 16; ++qq) {
            float4 v = xr[qq];
            s = fmaf(v.x, v.x, s); s = fmaf(v.y, v.y, s);
            s = fmaf(v.z, v.z, s); s = fmaf(v.w, v.w, s);
        }
        Ss[tid] = s;
    }

    const int r_lo = rt * 16 + g, r_hi = r_lo + 8;
    float bEl = 3.4e38f, bEh = 3.4e38f;
    int   bIl = 0x7fffffff, bIh = 0x7fffffff;

    #pragma unroll 1
    for (int q = 0; q < NQ; ++q) {
        __syncthreads();   // prior tiles + rmin fully consumed before restaging
        // --- stage W quarter hi/lo ---
        const float2* Wq2 = (const float2*)(W + (size_t)q * QCODES * DIM);
        for (int i = tid; i < QCODES * 32; i += THREADS) {
            int r = i >> 5, k2 = i & 31;
            float2 v = Wq2[r * 32 + k2];
            uint32_t hi, lo;
            split2pack(v.x, v.y, hi, lo);
            *(uint32_t*)(sm + OFF_WH + r * XSTRIDE_B + k2 * 4) = hi;
            *(uint32_t*)(sm + OFF_WL + r * XSTRIDE_B + k2 * 4) = lo;
        }
        __syncthreads();

        // --- mainloop: 3-pass bf16 MMA (Ah*Bh + Ah*Bl + Al*Bh), ldmatrix-fed ---
        float acc[8][4];
        #pragma unroll
        for (int t = 0; t < 8; ++t)
            acc[t][0] = acc[t][1] = acc[t][2] = acc[t][3] = 0.f;

        #pragma unroll
        for (int ks = 0; ks < 4; ++ks) {
            uint32_t ah0, ah1, ah2, ah3, al0, al1, al2, al3;
            LDSM_X4(ah0, ah1, ah2, ah3, aconst + (uint32_t)(OFF_XH + ks * 32));
            LDSM_X4(al0, al1, al2, al3, aconst + (uint32_t)(OFF_XL + ks * 32));
            #pragma unroll
            for (int tp = 0; tp < 4; ++tp) {
                uint32_t boff = bconst + (uint32_t)(tp * 16 * XSTRIDE_B + ks * 32);
                uint32_t bh0, bh1, bh2, bh3, bl0, bl1, bl2, bl3;
                LDSM_X4(bh0, bh1, bh2, bh3, boff + (uint32_t)OFF_WH);
                LDSM_X4(bl0, bl1, bl2, bl3, boff + (uint32_t)OFF_WL);
                float* aE = acc[2 * tp];
                float* aO = acc[2 * tp + 1];
                mma_bf16(aE[0], aE[1], aE[2], aE[3], ah0, ah1, ah2, ah3, bh0, bh1);
                mma_bf16(aE[0], aE[1], aE[2], aE[3], ah0, ah1, ah2, ah3, bl0, bl1);
                mma_bf16(aE[0], aE[1], aE[2], aE[3], al0, al1, al2, al3, bh0, bh1);
                mma_bf16(aO[0], aO[1], aO[2], aO[3], ah0, ah1, ah2, ah3, bh2, bh3);
                mma_bf16(aO[0], aO[1], aO[2], aO[3], ah0, ah1, ah2, ah3, bl2, bl3);
                mma_bf16(aO[0], aO[1], aO[2], aO[3], al0, al1, al2, al3, bh2, bh3);
            }
        }

        // --- in-register distances + per-row approx min ---
        const float S_lo = Ss[r_lo], S_hi = Ss[r_hi];
        float mn_lo = 3.4e38f, mn_hi = 3.4e38f;
        #pragma unroll
        for (int t = 0; t < 8; ++t) {
            int code = q * QCODES + ch * 64 + t * 8 + 2 * tig;
            float w20 = w2s[code], w21 = w2s[code + 1];
            acc[t][0] = (S_lo + w20) - 2.0f * acc[t][0];
            acc[t][1] = (S_lo + w21) - 2.0f * acc[t][1];
            acc[t][2] = (S_hi + w20) - 2.0f * acc[t][2];
            acc[t][3] = (S_hi + w21) - 2.0f * acc[t][3];
            mn_lo = fminf(mn_lo, fminf(acc[t][0], acc[t][1]));
            mn_hi = fminf(mn_hi, fminf(acc[t][2], acc[t][3]));
        }
        mn_lo = fminf(mn_lo, __shfl_xor_sync(0xffffffffu, mn_lo, 1));
        mn_lo = fminf(mn_lo, __shfl_xor_sync(0xffffffffu, mn_lo, 2));
        mn_hi = fminf(mn_hi, __shfl_xor_sync(0xffffffffu, mn_hi, 1));
        mn_hi = fminf(mn_hi, __shfl_xor_sync(0xffffffffu, mn_hi, 2));
        if (tig == 0) {
            rmin[ch * 128 + r_lo] = mn_lo;
            rmin[ch * 128 + r_hi] = mn_hi;
        }
        __syncthreads();
        float thr_lo = fminf(fminf(rmin[r_lo], rmin[128 + r_lo]), bEl) + EPS_CAND;
        float thr_hi = fminf(fminf(rmin[r_hi], rmin[128 + r_hi]), bEh) + EPS_CAND;

        // --- exact rescue (identical sequential-d fmaf chain as R4/R6) ---
        #pragma unroll
        for (int t = 0; t < 8; ++t) {
            #pragma unroll
            for (int j = 0; j < 2; ++j) {
                int code = q * QCODES + ch * 64 + t * 8 + 2 * tig + j;
                if (acc[t][j] <= thr_lo) {
                    float dot = 0.f;
                    const float4* xr = (const float4*)(Xs + r_lo * 64);
                    #pragma unroll
                    for (int qq = 0; qq < 16; ++qq) {
                        float4 wv = Wg4[code * 16 + qq], xv = xr[qq];
                        dot = fmaf(xv.x, wv.x, dot); dot = fmaf(xv.y, wv.y, dot);
                        dot = fmaf(xv.z, wv.z, dot); dot = fmaf(xv.w, wv.w, dot);
                    }
                    float de = (S_lo + w2s[code]) - 2.0f * dot;
                    if (de < bEl || (de == bEl && code < bIl)) { bEl = de; bIl = code; }
                }
                if (acc[t][2 + j] <= thr_hi) {
                    float dot = 0.f;
                    const float4* xr = (const float4*)(Xs + r_hi * 64);
                    #pragma unroll
                    for (int qq = 0; qq < 16; ++qq) {
                        float4 wv = Wg4[code * 16 + qq], xv = xr[qq];
                        dot = fmaf(xv.x, wv.x, dot); dot = fmaf(xv.y, wv.y, dot);
                        dot = fmaf(xv.z, wv.z, dot); dot = fmaf(xv.w, wv.w, dot);
                    }
                    float de = (S_hi + w2s[code]) - 2.0f * dot;
                    if (de < bEh || (de == bEh && code < bIh)) { bEh = de; bIh = code; }
                }
            }
        }
    }

    // --- reduce (exact best, lowest-index ties) over tig quad, then col halves ---
    #pragma unroll
    for (int off = 1; off <= 2; off <<= 1) {
        float ov = __shfl_xor_sync(0xffffffffu, bEl, off);
        int   oi = __shfl_xor_sync(0xffffffffu, bIl, off);
        if (ov < bEl || (ov == bEl && oi < bIl)) { bEl = ov; bIl = oi; }
        ov = __shfl_xor_sync(0xffffffffu, bEh, off);
        oi = __shfl_xor_sync(0xffffffffu, bIh, off);
        if (ov < bEh || (ov == bEh && oi < bIh)) { bEh = ov; bIh = oi; }
    }
    if (tig == 0) {
        cV[ch * 128 + r_lo] = bEl;  cI[ch * 128 + r_lo] = bIl;
        cV[ch * 128 + r_hi] = bEh;  cI[ch * 128 + r_hi] = bIh;
    }
    __syncthreads();

    // --- outputs: [loss | quantized N*64 | perplexity | indices N] ---
    // out_q = out + 1 is only 4B-aligned -> scalar STG.32 (R1 trap lesson).
    float* out_q = out + 1;
    float* out_i = out + 2 + (size_t)N_ROWS * DIM;

    if (tid < ROWS_PER_CTA) {
        float bv = cV[tid]; int bi = cI[tid];
        float v2 = cV[128 + tid]; int i2 = cI[128 + tid];
        if (v2 < bv || (v2 == bv && i2 < bi)) { bv = v2; bi = i2; }
        bidxs[tid] = bi;
        out_i[row0 + tid] = (float)bi;
        atomicAdd(&g_counts[bi], 1);
    }
    __syncthreads();

    float sq = 0.f;
    for (int i = tid; i < ROWS_PER_CTA * 16; i += THREADS) {
        int rr = i >> 4, qq = i & 15;
        int k = bidxs[rr];
        float4 wv = Wg4[k * 16 + qq];
        float4 xv = ((const float4*)(Xs + rr * 64))[qq];
        float* dst = out_q + (row0 + rr) * DIM + qq * 4;
        dst[0] = wv.x; dst[1] = wv.y; dst[2] = wv.z; dst[3] = wv.w;
        float dx = wv.x - xv.x, dy = wv.y - xv.y;
        float dz = wv.z - xv.z, dw = wv.w - xv.w;
        sq += dx * dx + dy * dy + dz * dz + dw * dw;
    }
    redf[tid] = sq;
    __syncthreads();
    #pragma unroll
    for (int s = THREADS / 2; s > 0; s >>= 1) {
        if (tid < s) redf[tid] += redf[tid + s];
        __syncthreads();
    }
    if (tid == 0) g_partials[bid] = redf[0];
}

__global__ void vq_final(float* __restrict__ out) {
    __shared__ float sh[KCODES];
    int t = threadIdx.x;

    float p = (float)g_counts[t] * (1.0f / (float)N_ROWS);
    sh[t] = -p * logf(p + 1e-10f);
    __syncthreads();
    for (int s = KCODES / 2; s > 0; s >>= 1) {
        if (t < s) sh[t] += sh[t + s];
        __syncthreads();
    }
    float ent = sh[0];
    __syncthreads();

    float ps = 0.f;
    for (int i = t; i < NCTA; i += KCODES) ps += g_partials[i];
    sh[t] = ps;
    __syncthreads();
    for (int s = KCODES / 2; s > 0; s >>= 1) {
        if (t < s) sh[t] += sh[t + s];
        __syncthreads();
    }
    if (t == 0) {
        float mse = sh[0] / (float)((size_t)N_ROWS * DIM);
        out[0] = 1.25f * mse;
        out[1 + (size_t)N_ROWS * DIM] = expf(ent) / (float)KCODES;
    }
}

extern "C" void kernel_launch(void* const* d_in, const int* in_sizes, int n_in,
                              void* d_out, int out_size)
{
    const float* X = (const float*)d_in[0];
    const float* W = (const float*)d_in[1];
    if (n_in >= 2 && in_sizes[0] == KCODES * DIM) {
        X = (const float*)d_in[1];
        W = (const float*)d_in[0];
    }
    float* out = (float*)d_out;
    (void)out_size;

    cudaFuncSetAttribute(vq_main, cudaFuncAttributeMaxDynamicSharedMemorySize,
                         SMEM_BYTES);

    vq_prep<<<1, KCODES>>>();
    vq_main<<<NCTA, THREADS, SMEM_BYTES>>>(X, W, out);
    vq_final<<<1, KCODES>>>(out);
}

// round 11
// speedup vs baseline: 1.4664x; 1.4590x over previous
#include <cuda_runtime.h>
#include <cstdint>

#define N_ROWS 262144
#define DIM 64
#define KCODES 512
#define ROWS_PER_CTA 128
#define NCTA (N_ROWS / ROWS_PER_CTA)   /* 2048 */
#define THREADS 256
#define QCODES 128

/* smem byte offsets: Xs[64][128] f32 | Wq[64][128] f32 | w2[512] | Ss[128] |
   bidx[128] | redf[256]  => 69632B -> 3 CTA/SM (208896 <= 227328) */
#define OFF_XS   0
#define OFF_WQ   32768
#define OFF_W2   65536
#define OFF_SS   67584
#define OFF_BIDX 68096
#define OFF_REDF 68608
#define SMEM_BYTES 69632

__device__ int   g_counts[KCODES];
__device__ float g_partials[NCTA];

// packed f32x2 (Blackwell FFMA2; ptxas never emits it from C++)
#define PACK_F32X2(out, lo, hi) \
    asm("mov.b64 %0, {%1, %2};" : "=l"(out) : "f"(lo), "f"(hi))
#define UNPACK_F32X2(lo, hi, in) \
    asm("mov.b64 {%0, %1}, %2;" : "=f"(lo), "=f"(hi) : "l"(in))
#define FMA_F32X2(d, a, b, c) \
    asm("fma.rn.f32x2 %0, %1, %2, %3;" : "=l"(d) : "l"(a), "l"(b), "l"(c))

__global__ void vq_prep() { g_counts[threadIdx.x] = 0; }

__global__ __launch_bounds__(THREADS, 3)
void vq_main(const float* __restrict__ X, const float* __restrict__ W,
             float* __restrict__ out)
{
    extern __shared__ char sm[];
    float* Xs    = (float*)(sm + OFF_XS);     // d-major [64][128]
    float* Wq    = (float*)(sm + OFF_WQ);     // d-major [64][128] (quarter)
    float* w2s   = (float*)(sm + OFF_W2);
    float* Ss    = (float*)(sm + OFF_SS);
    int*   bidxs = (int*)  (sm + OFF_BIDX);
    float* redf  = (float*)(sm + OFF_REDF);

    const int tid = threadIdx.x;
    const int tx = tid & 15, ty = tid >> 4;   // 16 col-threads x 16 row-threads
    const int bid = blockIdx.x;
    const size_t row0 = (size_t)bid * ROWS_PER_CTA;
    const float4* Wg4 = (const float4*)W;
    const float4* Xg4 = (const float4*)(X + row0 * DIM);

    // --- stage X transposed to d-major (stores: lanes vary row -> conflict-free)
    for (int i = tid; i < ROWS_PER_CTA * 16; i += THREADS) {
        int r = i & 127, d4 = i >> 7;
        float4 v = Xg4[r * 16 + d4];
        Xs[(d4 * 4 + 0) * 128 + r] = v.x;
        Xs[(d4 * 4 + 1) * 128 + r] = v.y;
        Xs[(d4 * 4 + 2) * 128 + r] = v.z;
        Xs[(d4 * 4 + 3) * 128 + r] = v.w;
    }

    // --- w2 for all 512 codes: sequential-d fmaf chain (proven identical) ---
    for (int c = tid; c < KCODES; c += THREADS) {
        float s = 0.f;
        #pragma unroll
        for (int qq = 0; qq < 16; ++qq) {
            float4 v = Wg4[c * 16 + qq];
            s = fmaf(v.x, v.x, s); s = fmaf(v.y, v.y, s);
            s = fmaf(v.z, v.z, s); s = fmaf(v.w, v.w, s);
        }
        w2s[c] = s;
    }
    __syncthreads();

    // --- S per row: sequential-d fmaf chain (lanes consecutive -> no conflicts)
    if (tid < ROWS_PER_CTA) {
        float s = 0.f;
        #pragma unroll
        for (int d = 0; d < DIM; ++d) {
            float x = Xs[d * 128 + tid];
            s = fmaf(x, x, s);
        }
        Ss[tid] = s;
    }
    __syncthreads();

    float S[8];
    #pragma unroll
    for (int i = 0; i < 8; ++i) S[i] = Ss[ty * 8 + i];

    float best[8]; int bidx[8];
    #pragma unroll
    for (int i = 0; i < 8; ++i) { best[i] = 3.4e38f; bidx[i] = 0; }

    const float4* Xs4 = (const float4*)Xs;
    const float4* Wq4 = (const float4*)Wq;
    const int ty2 = ty * 2;

    #pragma unroll 1
    for (int q = 0; q < 4; ++q) {
        __syncthreads();   // prior quarter fully consumed
        // --- stage W quarter transposed to d-major ---
        const float4* Wqg4 = (const float4*)(W + (size_t)q * QCODES * DIM);
        for (int i = tid; i < QCODES * 16; i += THREADS) {
            int k = i & 127, d4 = i >> 7;
            float4 v = Wqg4[k * 16 + d4];
            Wq[(d4 * 4 + 0) * 128 + k] = v.x;
            Wq[(d4 * 4 + 1) * 128 + k] = v.y;
            Wq[(d4 * 4 + 2) * 128 + k] = v.z;
            Wq[(d4 * 4 + 3) * 128 + k] = v.w;
        }
        __syncthreads();

        #pragma unroll 1
        for (int c = 0; c < 2; ++c) {   // two 64-col chunks per quarter
            // acc2[i2][j] = (dot[row ty*8+2*i2][col], dot[row ty*8+2*i2+1][col])
            unsigned long long acc2[4][4];
            #pragma unroll
            for (int i2 = 0; i2 < 4; ++i2)
                #pragma unroll
                for (int j = 0; j < 4; ++j) acc2[i2][j] = 0ull;

            const int cb4 = c * 16 + tx;
            #pragma unroll 4
            for (int d = 0; d < DIM; ++d) {
                float4 a0 = Xs4[d * 32 + ty2];
                float4 a1 = Xs4[d * 32 + ty2 + 1];
                float4 bv = Wq4[d * 32 + cb4];
                unsigned long long a2[4];
                PACK_F32X2(a2[0], a0.x, a0.y);
                PACK_F32X2(a2[1], a0.z, a0.w);
                PACK_F32X2(a2[2], a1.x, a1.y);
                PACK_F32X2(a2[3], a1.z, a1.w);
                float b[4] = {bv.x, bv.y, bv.z, bv.w};
                #pragma unroll
                for (int j = 0; j < 4; ++j) {
                    unsigned long long b2;
                    PACK_F32X2(b2, b[j], b[j]);
                    #pragma unroll
                    for (int i2 = 0; i2 < 4; ++i2)
                        FMA_F32X2(acc2[i2][j], a2[i2], b2, acc2[i2][j]);
                }
            }

            // dist = fl(fl(S + w2) - 2*dot), strict-< first-min (codes ascending)
            #pragma unroll
            for (int j = 0; j < 4; ++j) {
                int code = q * QCODES + c * 64 + tx * 4 + j;
                float w2c = w2s[code];
                #pragma unroll
                for (int i2 = 0; i2 < 4; ++i2) {
                    float dlo, dhi;
                    UNPACK_F32X2(dlo, dhi, acc2[i2][j]);
                    int i = i2 * 2;
                    float d0 = (S[i] + w2c) - 2.0f * dlo;      // fl(2a)=2a exact
                    if (d0 < best[i]) { best[i] = d0; bidx[i] = code; }
                    float d1 = (S[i + 1] + w2c) - 2.0f * dhi;
                    if (d1 < best[i + 1]) { best[i + 1] = d1; bidx[i + 1] = code; }
                }
            }
        }
    }

    // --- argmin reduce over the 16 tx-threads (xor stays within ty group) ---
    #pragma unroll
    for (int i = 0; i < 8; ++i) {
        #pragma unroll
        for (int off = 8; off > 0; off >>= 1) {
            float ov = __shfl_xor_sync(0xffffffffu, best[i], off);
            int   oi = __shfl_xor_sync(0xffffffffu, bidx[i], off);
            if (ov < best[i] || (ov == best[i] && oi < bidx[i])) {
                best[i] = ov; bidx[i] = oi;
            }
        }
    }
    if (tx == 0) {
        #pragma unroll
        for (int i = 0; i < 8; ++i) bidxs[ty * 8 + i] = bidx[i];
    }
    __syncthreads();

    // --- outputs: [loss | quantized N*64 | perplexity | indices N] ---
    // out_q = out + 1 is only 4B-aligned -> scalar STG.32 (R1 trap lesson).
    float* out_q = out + 1;
    float* out_i = out + 2 + (size_t)N_ROWS * DIM;

    if (tid < ROWS_PER_CTA) {
        int k = bidxs[tid];
        out_i[row0 + tid] = (float)k;
        atomicAdd(&g_counts[k], 1);
    }
    __syncthreads();

    // quantized gather + MSE partial; X and W both read from global (coalesced,
    // L1/L2-hot) to avoid the d-major smem conflict pattern.
    float sq = 0.f;
    for (int i = tid; i < ROWS_PER_CTA * 16; i += THREADS) {
        int rr = i >> 4, qq = i & 15;
        int k = bidxs[rr];
        float4 wv = Wg4[k * 16 + qq];
        float4 xv = Xg4[rr * 16 + qq];
        float* dst = out_q + (row0 + rr) * DIM + qq * 4;
        dst[0] = wv.x; dst[1] = wv.y; dst[2] = wv.z; dst[3] = wv.w;
        float dx = wv.x - xv.x, dy = wv.y - xv.y;
        float dz = wv.z - xv.z, dw = wv.w - xv.w;
        sq += dx * dx + dy * dy + dz * dz + dw * dw;
    }
    redf[tid] = sq;
    __syncthreads();
    #pragma unroll
    for (int s = THREADS / 2; s > 0; s >>= 1) {
        if (tid < s) redf[tid] += redf[tid + s];
        __syncthreads();
    }
    if (tid == 0) g_partials[bid] = redf[0];
}

__global__ void vq_final(float* __restrict__ out) {
    __shared__ float sh[KCODES];
    int t = threadIdx.x;

    float p = (float)g_counts[t] * (1.0f / (float)N_ROWS);
    sh[t] = -p * logf(p + 1e-10f);
    __syncthreads();
    for (int s = KCODES / 2; s > 0; s >>= 1) {
        if (t < s) sh[t] += sh[t + s];
        __syncthreads();
    }
    float ent = sh[0];
    __syncthreads();

    float ps = 0.f;
    for (int i = t; i < NCTA; i += KCODES) ps += g_partials[i];
    sh[t] = ps;
    __syncthreads();
    for (int s = KCODES / 2; s > 0; s >>= 1) {
        if (t < s) sh[t] += sh[t + s];
        __syncthreads();
    }
    if (t == 0) {
        float mse = sh[0] / (float)((size_t)N_ROWS * DIM);
        out[0] = 1.25f * mse;                              // q_loss + 0.25*e_loss
        out[1 + (size_t)N_ROWS * DIM] = expf(ent) / (float)KCODES;
    }
}

extern "C" void kernel_launch(void* const* d_in, const int* in_sizes, int n_in,
                              void* d_out, int out_size)
{
    const float* X = (const float*)d_in[0];
    const float* W = (const float*)d_in[1];
    if (n_in >= 2 && in_sizes[0] == KCODES * DIM) {  // defensive input-order check
        X = (const float*)d_in[1];
        W = (const float*)d_in[0];
    }
    float* out = (float*)d_out;
    (void)out_size;

    cudaFuncSetAttribute(vq_main, cudaFuncAttributeMaxDynamicSharedMemorySize,
                         SMEM_BYTES);

    vq_prep<<<1, KCODES>>>();
    vq_main<<<NCTA, THREADS, SMEM_BYTES>>>(X, W, out);
    vq_final<<<1, KCODES>>>(out);
}